// round 5
// baseline (speedup 1.0000x reference)
#include <cuda_runtime.h>
#include <cstddef>

#define NN 100000

// Scratch (device globals, referenced directly from device code)
__device__ float g_deg[NN];
__device__ float g_agg[(size_t)NN * 128];
__device__ float g_y[(size_t)NN * 128];
__device__ float g_h[(size_t)NN * 128];
__device__ int   g_is64;   // 1 if edge_index is int64, 0 if int32

// ---------------------------------------------------------------------------
// dtype detection: int64 values < 100000 have zero high words; int32 layout
// puts a random index (nonzero w.p. ~1-1e-5) in those slots.
// ---------------------------------------------------------------------------
__global__ void detect_kernel(const int* __restrict__ ei32) {
    if (blockIdx.x == 0 && threadIdx.x == 0) {
        int is64 = 1;
        for (int i = 0; i < 64; i++)
            if (ei32[2 * i + 1] != 0) { is64 = 0; break; }
        g_is64 = is64;
    }
}

// Load edge endpoint (half=0: src, half=1: dst), clamped to [0, n)
__device__ __forceinline__ int load_idx(const void* ei, int pos, int nE,
                                        int half, int n) {
    size_t idx = (size_t)half * nE + pos;
    long long v;
    if (g_is64) v = ((const long long*)ei)[idx];
    else        v = ((const int*)ei)[idx];
    if (v < 0) v = 0;
    if (v >= n) v = n - 1;
    return (int)v;
}

// ---------------------------------------------------------------------------
// zero kernels (float4 granularity; counts are exact multiples of 4)
// ---------------------------------------------------------------------------
__global__ void zero_deg_kernel(int n4) {
    int i = blockIdx.x * blockDim.x + threadIdx.x;
    if (i < n4) ((float4*)g_deg)[i] = make_float4(0.f, 0.f, 0.f, 0.f);
}
__global__ void zero_agg_kernel(int n4) {
    int i = blockIdx.x * blockDim.x + threadIdx.x;
    if (i < n4) ((float4*)g_agg)[i] = make_float4(0.f, 0.f, 0.f, 0.f);
}

// ---------------------------------------------------------------------------
// degree: one thread per edge, atomicAdd (REDG) on dst
// ---------------------------------------------------------------------------
__global__ void deg_kernel(const void* __restrict__ ei, int nE, int n) {
    int e = blockIdx.x * blockDim.x + threadIdx.x;
    if (e < nE) atomicAdd(&g_deg[load_idx(ei, e, nE, 1, n)], 1.0f);
}

// ---------------------------------------------------------------------------
// scatter-add: D/4 lanes per edge, float4 gather from g_y + 4 scalar
// atomicAdds (REDG.ADD.F32) into g_agg
// ---------------------------------------------------------------------------
template <int D>
__global__ void scatter_kernel(const void* __restrict__ ei, int nE, int n) {
    constexpr int LPE = D / 4;
    long long t = (long long)blockIdx.x * blockDim.x + threadIdx.x;
    int e = (int)(t / LPE);
    int lane = (int)(t % LPE);
    if (e >= nE) return;
    int src = load_idx(ei, e, nE, 0, n);
    int dst = load_idx(ei, e, nE, 1, n);
    float4 v = ((const float4*)(g_y + (size_t)src * D))[lane];
    float* p = g_agg + (size_t)dst * D + lane * 4;
    atomicAdd(p + 0, v.x);
    atomicAdd(p + 1, v.y);
    atomicAdd(p + 2, v.z);
    atomicAdd(p + 3, v.w);
}

// ---------------------------------------------------------------------------
// K-chunked smem GEMM with STATIC shared memory (<48 KB, no attribute calls).
//   C[n, DOUT] = A[n, DIN] @ W[DIN, DOUT]  (+ optional mean-agg epilogue)
// A source:  ASRC==0 -> Aarg (harness input),  ASRC==1 -> g_h
// C dest:    CDST==0 -> Carg (harness output), CDST==1 -> g_y, CDST==2 -> g_h
// Epilogue:  C += g_agg[node]/max(g_deg[node],1) + bias; optional ReLU.
// Block: 256 threads / 8 warps, 32 nodes per block, 4 nodes per warp.
// Each lane owns VEC = DOUT/32 consecutive output columns.
// ---------------------------------------------------------------------------
template <int DIN, int DOUT, int ASRC, int CDST, bool EPI, bool RELU>
__global__ void gemm_kernel(const float* __restrict__ Aarg,
                            const float* __restrict__ W,
                            const float* __restrict__ bias,
                            float* __restrict__ Carg, int n) {
    constexpr int KC = 64;            // k-chunk
    constexpr int NODES = 32;
    __shared__ float sW[KC * DOUT];   // 32 KB (DOUT=128) / 16 KB (DOUT=64)
    __shared__ float sA[NODES * KC];  // 8 KB

    const float* A = (ASRC == 0) ? Aarg : (const float*)g_h;
    float* C = (CDST == 0) ? Carg : (CDST == 1) ? (float*)g_y : (float*)g_h;

    const int tid = threadIdx.x;
    const int node0 = blockIdx.x * NODES;
    constexpr int VEC = DOUT / 32;    // 4 or 2
    constexpr int NPW = NODES / 8;    // 4 nodes per warp
    const int warp = tid >> 5;
    const int lane = tid & 31;

    float acc[NPW][VEC];
#pragma unroll
    for (int m = 0; m < NPW; m++)
#pragma unroll
        for (int v = 0; v < VEC; v++) acc[m][v] = 0.f;

    for (int kc = 0; kc < DIN; kc += KC) {
        const float4* Wsrc = (const float4*)(W + (size_t)kc * DOUT);
        for (int i = tid; i < KC * DOUT / 4; i += blockDim.x)
            ((float4*)sW)[i] = Wsrc[i];

        for (int i = tid; i < NODES * KC / 4; i += blockDim.x) {
            int row = i / (KC / 4);
            int col = i % (KC / 4);
            int node = node0 + row;
            float4 v = make_float4(0.f, 0.f, 0.f, 0.f);
            if (node < n)
                v = ((const float4*)(A + (size_t)node * DIN + kc))[col];
            ((float4*)sA)[i] = v;
        }
        __syncthreads();

        const float* sAw = sA + warp * NPW * KC;
#pragma unroll 4
        for (int k = 0; k < KC; k++) {
            float wv[VEC];
#pragma unroll
            for (int v = 0; v < VEC; v++) wv[v] = sW[k * DOUT + lane * VEC + v];
#pragma unroll
            for (int m = 0; m < NPW; m++) {
                float a = sAw[m * KC + k];
#pragma unroll
                for (int v = 0; v < VEC; v++) acc[m][v] = fmaf(a, wv[v], acc[m][v]);
            }
        }
        __syncthreads();
    }

#pragma unroll
    for (int m = 0; m < NPW; m++) {
        int node = node0 + warp * NPW + m;
        if (node >= n) break;
        float rdeg = 0.f;
        if (EPI) rdeg = 1.0f / fmaxf(g_deg[node], 1.0f);
#pragma unroll
        for (int v = 0; v < VEC; v++) {
            int col = lane * VEC + v;
            float r = acc[m][v];
            if (EPI) r += g_agg[(size_t)node * DOUT + col] * rdeg + bias[col];
            if (RELU) r = fmaxf(r, 0.f);
            C[(size_t)node * DOUT + col] = r;
        }
    }
}

// ---------------------------------------------------------------------------
// launch — kernel launches only; no allocations, no attribute/symbol APIs
// ---------------------------------------------------------------------------
extern "C" void kernel_launch(void* const* d_in, const int* in_sizes, int n_in,
                              void* d_out, int out_size) {
    const float* x   = (const float*)d_in[0];
    const void*  ei  = d_in[1];               // int32 or int64, detected on-device
    const float* W1l = (const float*)d_in[2];
    const float* W1r = (const float*)d_in[3];
    const float* b1  = (const float*)d_in[4];
    const float* W2l = (const float*)d_in[5];
    const float* W2r = (const float*)d_in[6];
    const float* b2  = (const float*)d_in[7];
    float* out = (float*)d_out;

    const int n  = in_sizes[0] / 128;   // 100000
    const int nE = in_sizes[1] / 2;     // 1600000

    const int ZB = 256;
    const int GB = (n + 31) / 32;       // GEMM grid (3125)

    detect_kernel<<<1, 32>>>((const int*)ei);

    zero_deg_kernel<<<(n / 4 + ZB - 1) / ZB, ZB>>>(n / 4);
    zero_agg_kernel<<<(n * 32 + ZB - 1) / ZB, ZB>>>(n * 32);

    deg_kernel<<<(nE + 255) / 256, 256>>>(ei, nE, n);

    // ---- Layer 1 ----
    gemm_kernel<128, 128, 0, 1, false, false><<<GB, 256>>>(x, W1l, nullptr, nullptr, n);
    {
        long long threads = (long long)nE * 32;
        scatter_kernel<128><<<(unsigned)((threads + 255) / 256), 256>>>(ei, nE, n);
    }
    gemm_kernel<128, 128, 0, 2, true, true><<<GB, 256>>>(x, W1r, b1, nullptr, n);

    // ---- Layer 2 ----
    zero_agg_kernel<<<(n * 16 + ZB - 1) / ZB, ZB>>>(n * 16);
    gemm_kernel<128, 64, 1, 1, false, false><<<GB, 256>>>(nullptr, W2l, nullptr, nullptr, n);
    {
        long long threads = (long long)nE * 16;
        scatter_kernel<64><<<(unsigned)((threads + 255) / 256), 256>>>(ei, nE, n);
    }
    gemm_kernel<128, 64, 1, 0, true, false><<<GB, 256>>>(nullptr, W2r, b2, out, n);
}